// round 14
// baseline (speedup 1.0000x reference)
#include <cuda_runtime.h>
#include <cuda_bf16.h>
#include <math.h>
#include <stdint.h>

typedef unsigned long long ull;

// ===================== helpers =====================
__device__ __forceinline__ uint32_t smem_u32(const void* p) {
    uint32_t a;
    asm("{ .reg .u64 t; cvta.to.shared.u64 t, %1; cvt.u32.u64 %0, t; }" : "=r"(a) : "l"(p));
    return a;
}

#define LOG2E 1.4426950408889634f
__device__ __forceinline__ float ex2f(float x) { float r; asm("ex2.approx.ftz.f32 %0, %1;" : "=f"(r) : "f"(x)); return r; }
__device__ __forceinline__ float rcpf(float x) { float r; asm("rcp.approx.ftz.f32 %0, %1;" : "=f"(r) : "f"(x)); return r; }
__device__ __forceinline__ float tanhx(float x) { float r; asm("tanh.approx.f32 %0, %1;" : "=f"(r) : "f"(x)); return r; }
__device__ __forceinline__ float sigx(float x)  { return fmaf(tanhx(0.5f * x), 0.5f, 0.5f); }

// bf16x2 pack/unpack (lo = even element, hi = odd element)
__device__ __forceinline__ uint32_t packbf2(float lo, float hi) {
    uint32_t r;
    asm("cvt.rn.bf16x2.f32 %0, %1, %2;" : "=r"(r) : "f"(hi), "f"(lo));
    return r;
}
__device__ __forceinline__ float unpklo(uint32_t p) { return __uint_as_float(p << 16); }
__device__ __forceinline__ float unpkhi(uint32_t p) { return __uint_as_float(p & 0xffff0000u); }

// mma.sync m16n8k16 bf16 (sm_80+, no arch suffix)
__device__ __forceinline__ void mma16816(float* c, const uint32_t* a, const uint32_t* b) {
    asm volatile(
        "mma.sync.aligned.m16n8k16.row.col.f32.bf16.bf16.f32 "
        "{%0,%1,%2,%3}, {%4,%5,%6,%7}, {%8,%9}, {%0,%1,%2,%3};"
        : "+f"(c[0]), "+f"(c[1]), "+f"(c[2]), "+f"(c[3])
        : "r"(a[0]), "r"(a[1]), "r"(a[2]), "r"(a[3]), "r"(b[0]), "r"(b[1]));
}
#define LDSM4(r, a) \
    asm volatile("ldmatrix.sync.aligned.m8n8.x4.shared.b16 {%0,%1,%2,%3}, [%4];" \
        : "=r"((r)[0]), "=r"((r)[1]), "=r"((r)[2]), "=r"((r)[3]) : "r"(a))
#define LDSM2(r, a) \
    asm volatile("ldmatrix.sync.aligned.m8n8.x2.shared.b16 {%0,%1}, [%2];" \
        : "=r"((r)[0]), "=r"((r)[1]) : "r"(a))

#define CP16(dst, src) \
    asm volatile("cp.async.cg.shared.global [%0], [%1], 16;" :: "r"(dst), "l"(src) : "memory")
#define CP_COMMIT() asm volatile("cp.async.commit_group;" ::: "memory")
#define CP_WAIT1()  asm volatile("cp.async.wait_group 1;" ::: "memory")
#define CP_WAIT0()  asm volatile("cp.async.wait_group 0;" ::: "memory")

// ===================== global scratch =====================
// packed weights: [matgate 6][n 192][k 192] bf16
__device__ __nv_bfloat16 g_Wpk[6 * 192 * 192];
__device__ float g_bias[6 * 192];            // [matgate][n], zero-padded
__device__ __nv_bfloat16 g_hdec[88473600];   // [2048][240][180] bf16
__device__ float g_part[16 * 2048 * 40];

// ===================== smem layout (bytes) =====================
// A: [128 rows][200 bf16] (400B rows, conflict-free for ldmatrix)
#define OA    0
// B: 2 slots x [192 n][40 bf16] (80B rows = 32 k + 16B pad)
#define OB    51200
#define BSLOT 15360
#define SMEM_TOT 81920

// ===================== prep: pack weights (bf16) + bias =====================
__global__ void prep_weights(const float* __restrict__ We, const float* __restrict__ bie,
                             const float* __restrict__ bhe, const float* __restrict__ Wd,
                             const float* __restrict__ bid, const float* __restrict__ bhd) {
    const int gb[3] = {0, 360, 540};   // torch gates i,f,g,o -> keep i,g,o (f dead: c_prev=0)
    int idx = blockIdx.x * blockDim.x + threadIdx.x;
    int stride = gridDim.x * blockDim.x;
    for (int i = idx; i < 6 * 192 * 192; i += stride) {
        int k = i % 192, n = (i / 192) % 192, g = (i / 36864) % 3, mat = i / 110592;
        float v = 0.f;
        if (n < 180 && k < 180) v = (mat ? Wd : We)[(gb[g] + n) * 180 + k];
        g_Wpk[(size_t)(mat * 3 + g) * 36864 + (size_t)n * 192 + k] = __float2bfloat16(v);
    }
    for (int i = idx; i < 6 * 192; i += stride) {
        int n = i % 192, g = (i / 192) % 3, mat = i / 576;
        float v = 0.f;
        if (n < 180) v = (mat ? bid : bie)[gb[g] + n] + (mat ? bhd : bhe)[gb[g] + n];
        g_bias[(mat * 3 + g) * 192 + n] = v;
    }
}

// dummies: shift fused_encdec to in-call launch position 4 so ncu samples it
__global__ void dummy_k() {}

// ===================== B chunk staging (k32, 2 slots) =====================
__device__ __forceinline__ void stage_chunk(uint32_t sb, int tid, int c) {
    int mg6 = c / 6, kc = c % 6;             // matgate 0..5, k-chunk 0..5
    const char* base = (const char*)g_Wpk + (size_t)mg6 * 73728;
    uint32_t dstb = sb + OB + (uint32_t)(c & 1) * BSLOT;
#pragma unroll
    for (int it = 0; it < 3; it++) {
        int idx = tid + it * 256;            // 0..767
        int j = idx & 3;                     // 16B piece within 64B row chunk
        int n = idx >> 2;                    // 0..191
        const void* src = base + (size_t)n * 384 + kc * 64 + j * 16;
        uint32_t dst = dstb + (uint32_t)n * 80 + (uint32_t)j * 16;
        CP16(dst, src);
    }
}

// ===================== fused enc -> softmax -> dec (M=128 tile) =====================
__global__ void __launch_bounds__(256, 1) fused_encdec(const float* __restrict__ x) {
    extern __shared__ char sm[];
    const uint32_t sb = smem_u32(sm);
    const int tid = threadIdx.x, lane = tid & 31, wid = tid >> 5;
    const int mg = wid >> 2;                 // 0..1 : M row group (64 rows)
    const int ng = wid & 3;                  // 0..3 : N col group (48 cols)
    const int b = blockIdx.y, t0 = blockIdx.x * 120;

    // Build A plane from x[b][k][t0+t]; rows t>=120 and cols k>=180 zero
    for (int i = tid; i < 192 * 128; i += 256) {
        int k = i >> 7, t = i & 127;
        float v = (k < 180 && t < 120) ? x[((size_t)b * 180 + k) * 240 + t0 + t] : 0.f;
        *(__nv_bfloat16*)(sm + OA + t * 400 + k * 2) = __float2bfloat16(v);
    }

    // ldmatrix per-lane offsets
    const int rit = lane & 7, grp = lane >> 3;
    const uint32_t aoff = (uint32_t)((rit + (grp & 1) * 8) * 400 + (grp >> 1) * 16);
    const int l2 = lane & 15;
    const uint32_t boff = (uint32_t)((l2 & 7) * 80 + (l2 >> 3) * 16);
    const uint32_t mgbase = (uint32_t)(mg * 64 * 400);
    const uint32_t ngbase = (uint32_t)(ng * 48 * 80);

    stage_chunk(sb, tid, 0);
    CP_COMMIT();

    int c = 0;
    uint32_t sval[48];                       // bf16x2-packed sig(i) / tanh(c)
    for (int mat = 0; mat < 2; mat++) {
        for (int g = 0; g < 3; g++) {
            float acc[96];
#pragma unroll
            for (int v = 0; v < 96; v++) acc[v] = 0.f;

            for (int kc = 0; kc < 6; kc++, c++) {
                if (c + 1 < 36) { stage_chunk(sb, tid, c + 1); CP_COMMIT(); CP_WAIT1(); }
                else CP_WAIT0();
                __syncthreads();   // chunk c visible; also orders A-plane writes
                uint32_t Bbase = sb + OB + (uint32_t)(c & 1) * BSLOT;
#pragma unroll
                for (int s = 0; s < 2; s++) {
                    const int k0 = kc * 32 + s * 16;
                    uint32_t Ah[4][4];
#pragma unroll
                    for (int mi = 0; mi < 4; mi++) {
                        uint32_t a = sb + OA + mgbase + (uint32_t)(mi * 6400) +
                                     (uint32_t)(k0 * 2) + aoff;
                        LDSM4(Ah[mi], a);
                    }
                    uint32_t Bh[6][2];
#pragma unroll
                    for (int ni = 0; ni < 6; ni++) {
                        uint32_t ba = Bbase + ngbase + (uint32_t)(ni * 640) +
                                      (uint32_t)(s * 32) + boff;
                        LDSM2(Bh[ni], ba);
                    }
#pragma unroll
                    for (int mi = 0; mi < 4; mi++)
#pragma unroll
                        for (int ni = 0; ni < 6; ni++)
                            mma16816(&acc[(mi * 6 + ni) * 4], Ah[mi], Bh[ni]);
                }
                __syncthreads();   // all warps done with slot (c&1) before restage
            }

            // ---- gate epilogue ----
            const float* bias = g_bias + (mat * 3 + g) * 192;
#pragma unroll
            for (int mi = 0; mi < 4; mi++)
#pragma unroll
                for (int ni = 0; ni < 6; ni++) {
                    int nb = ng * 48 + ni * 8 + (lane & 3) * 2;
                    float b0 = __ldg(bias + nb), b1 = __ldg(bias + nb + 1);
#pragma unroll
                    for (int p2 = 0; p2 < 2; p2++) {
                        int v0 = (mi * 6 + ni) * 4 + 2 * p2;
                        int si = (mi * 6 + ni) * 2 + p2;
                        if (g == 0) {
                            sval[si] = packbf2(sigx(acc[v0] + b0), sigx(acc[v0 + 1] + b1));
                        } else if (g == 1) {
                            float s0 = unpklo(sval[si]), s1 = unpkhi(sval[si]);
                            sval[si] = packbf2(tanhx(s0 * tanhx(acc[v0] + b0)),
                                               tanhx(s1 * tanhx(acc[v0 + 1] + b1)));
                        } else {
                            float tc0 = unpklo(sval[si]), tc1 = unpkhi(sval[si]);
                            float h0 = sigx(acc[v0] + b0) * tc0;
                            float h1 = sigx(acc[v0 + 1] + b1) * tc1;
                            int t = mg * 64 + mi * 16 + (lane >> 2) + p2 * 8;
                            *(uint32_t*)(sm + OA + t * 400 + nb * 2) = packbf2(h0, h1);
                        }
                    }
                }

            if (g == 2) {
                __syncthreads();   // all h written to A plane
                if (mat == 0) {
                    // per-row softmax over n (0..179), in place; warp owns 16 rows
                    for (int rr = 0; rr < 16; rr++) {
                        int t = wid * 16 + rr;
                        uint32_t* row = (uint32_t*)(sm + OA + t * 400);
                        float f0[3], f1[3];
                        float m = -1e30f;
#pragma unroll
                        for (int j = 0; j < 3; j++) {
                            int idx = lane + j * 32;
                            uint32_t u = (idx < 90) ? row[idx] : 0u;
                            f0[j] = (idx < 90) ? unpklo(u) : -1e30f;
                            f1[j] = (idx < 90) ? unpkhi(u) : -1e30f;
                            m = fmaxf(m, fmaxf(f0[j], f1[j]));
                        }
#pragma unroll
                        for (int d = 16; d >= 1; d >>= 1)
                            m = fmaxf(m, __shfl_xor_sync(0xffffffffu, m, d));
                        float s = 0.f;
#pragma unroll
                        for (int j = 0; j < 3; j++) {
                            if (lane + j * 32 < 90) {
                                f0[j] = ex2f((f0[j] - m) * LOG2E);
                                f1[j] = ex2f((f1[j] - m) * LOG2E);
                                s += f0[j] + f1[j];
                            }
                        }
#pragma unroll
                        for (int d = 16; d >= 1; d >>= 1)
                            s += __shfl_xor_sync(0xffffffffu, s, d);
                        float inv = rcpf(s);
#pragma unroll
                        for (int j = 0; j < 3; j++) {
                            int idx = lane + j * 32;
                            if (idx < 90) row[idx] = packbf2(f0[j] * inv, f1[j] * inv);
                        }
                    }
                    // next chunk-loop sync orders these writes vs ldmatrix
                } else {
                    // h_dec[b][t0+t][n] <- A rows (bf16, coalesced)
                    for (int i = tid; i < 120 * 90; i += 256) {
                        int t = i / 90, j = i % 90;
                        uint32_t w = *(uint32_t*)(sm + OA + t * 400 + j * 4);
                        ((uint32_t*)g_hdec)[(size_t)(b * 240 + t0 + t) * 90 + j] = w;
                    }
                }
            }
        }
    }
}

// ---------------- output GEMM, split-K partials (bf16 h loads) ----------------
__device__ __forceinline__ ull ffma2(ull a, ull b, ull c) {
    ull d;
    asm("fma.rn.f32x2 %0, %1, %2, %3;" : "=l"(d) : "l"(a), "l"(b), "l"(c));
    return d;
}
__device__ __forceinline__ float2 unpackf2(ull v) {
    float2 r;
    asm("mov.b64 {%0, %1}, %2;" : "=f"(r.x), "=f"(r.y) : "l"(v));
    return r;
}

__global__ void __launch_bounds__(256) out_gemm(const float* __restrict__ Wout) {
    __shared__ float Hc[64][62];
    __shared__ float Wc[40][62];
    const int ks = blockIdx.x;
    const int b0 = blockIdx.y * 64;
    const int k0 = ks * 2700;
    const int tid = threadIdx.x;
    const int bg = tid % 32;
    const int ng = tid / 32;

    ull acc2[2][5];
#pragma unroll
    for (int bi = 0; bi < 2; bi++)
#pragma unroll
        for (int q = 0; q < 5; q++) acc2[bi][q] = 0ull;

    for (int cc = 0; cc < 45; cc++) {
        __syncthreads();
        const int kb = k0 + cc * 60;
        for (int i = tid; i < 64 * 30; i += 256) {
            int bb = i / 30, k2 = i % 30;
            __nv_bfloat162 p = *(const __nv_bfloat162*)&g_hdec[(size_t)(b0 + bb) * 43200 + kb + k2 * 2];
            Hc[bb][k2 * 2]     = __bfloat162float(p.x);
            Hc[bb][k2 * 2 + 1] = __bfloat162float(p.y);
        }
        for (int i = tid; i < 40 * 60; i += 256) {
            int n = i / 60, k = i % 60;
            Wc[n][k] = Wout[(size_t)n * 43200 + kb + k];
        }
        __syncthreads();
#pragma unroll 6
        for (int kp = 0; kp < 30; kp++) {
            ull h0 = *(const ull*)&Hc[bg][kp * 2];
            ull h1 = *(const ull*)&Hc[bg + 32][kp * 2];
#pragma unroll
            for (int q = 0; q < 5; q++) {
                ull w = *(const ull*)&Wc[ng * 5 + q][kp * 2];
                acc2[0][q] = ffma2(h0, w, acc2[0][q]);
                acc2[1][q] = ffma2(h1, w, acc2[1][q]);
            }
        }
    }
#pragma unroll
    for (int bi = 0; bi < 2; bi++)
#pragma unroll
        for (int q = 0; q < 5; q++) {
            float2 p = unpackf2(acc2[bi][q]);
            g_part[((size_t)ks * 2048 + b0 + bg + 32 * bi) * 40 + ng * 5 + q] = p.x + p.y;
        }
}

__global__ void reduce_softmax(const float* __restrict__ bout, float* __restrict__ out) {
    __shared__ float smv[40];
    const int b = blockIdx.x;
    const int n = threadIdx.x;
    float l = bout[n];
#pragma unroll
    for (int ks = 0; ks < 16; ks++) l += g_part[((size_t)ks * 2048 + b) * 40 + n];
    smv[n] = l;
    __syncthreads();
    const int g0 = (n / 10) * 10;
    float m = smv[g0];
#pragma unroll
    for (int i = 1; i < 10; i++) m = fmaxf(m, smv[g0 + i]);
    float s = 0.f;
#pragma unroll
    for (int i = 0; i < 10; i++) s += expf(smv[g0 + i] - m);
    out[(size_t)b * 40 + n] = expf(l - m) / s;
}

// ---------------- launcher ----------------
extern "C" void kernel_launch(void* const* d_in, const int* in_sizes, int n_in,
                              void* d_out, int out_size) {
    const float* x    = (const float*)d_in[0];
    const float* Wenc = (const float*)d_in[1];
    const float* bie  = (const float*)d_in[2];
    const float* bhe  = (const float*)d_in[3];
    const float* Wdec = (const float*)d_in[4];
    const float* bid  = (const float*)d_in[5];
    const float* bhd  = (const float*)d_in[6];
    const float* Wout = (const float*)d_in[7];
    const float* bout = (const float*)d_in[8];
    float* out = (float*)d_out;

    cudaFuncSetAttribute(fused_encdec, cudaFuncAttributeMaxDynamicSharedMemorySize, SMEM_TOT);

    prep_weights<<<256, 256>>>(Wenc, bie, bhe, Wdec, bid, bhd);
    dummy_k<<<1, 32>>>();
    dummy_k<<<1, 32>>>();   // fused_encdec at in-call launch #4 (ncu steering)
    fused_encdec<<<dim3(2, 2048), 256, SMEM_TOT>>>(x);
    out_gemm<<<dim3(16, 32), 256>>>(Wout);
    reduce_softmax<<<2048, 40>>>(bout, out);
}

// round 15
// speedup vs baseline: 1.5777x; 1.5777x over previous
#include <cuda_runtime.h>
#include <cuda_bf16.h>
#include <math.h>
#include <stdint.h>

typedef unsigned long long ull;

// ===================== helpers =====================
__device__ __forceinline__ uint32_t smem_u32(const void* p) {
    uint32_t a;
    asm("{ .reg .u64 t; cvta.to.shared.u64 t, %1; cvt.u32.u64 %0, t; }" : "=r"(a) : "l"(p));
    return a;
}

#define LOG2E 1.4426950408889634f
__device__ __forceinline__ float ex2f(float x) { float r; asm("ex2.approx.ftz.f32 %0, %1;" : "=f"(r) : "f"(x)); return r; }
__device__ __forceinline__ float tanhx(float x) { float r; asm("tanh.approx.f32 %0, %1;" : "=f"(r) : "f"(x)); return r; }
__device__ __forceinline__ float sigx(float x)  { return fmaf(tanhx(0.5f * x), 0.5f, 0.5f); }

// mma.sync m16n8k16 bf16 (sm_80+, no arch suffix)
__device__ __forceinline__ void mma16816(float* c, const uint32_t* a, const uint32_t* b) {
    asm volatile(
        "mma.sync.aligned.m16n8k16.row.col.f32.bf16.bf16.f32 "
        "{%0,%1,%2,%3}, {%4,%5,%6,%7}, {%8,%9}, {%0,%1,%2,%3};"
        : "+f"(c[0]), "+f"(c[1]), "+f"(c[2]), "+f"(c[3])
        : "r"(a[0]), "r"(a[1]), "r"(a[2]), "r"(a[3]), "r"(b[0]), "r"(b[1]));
}
#define LDSM4(r, a) \
    asm volatile("ldmatrix.sync.aligned.m8n8.x4.shared.b16 {%0,%1,%2,%3}, [%4];" \
        : "=r"((r)[0]), "=r"((r)[1]), "=r"((r)[2]), "=r"((r)[3]) : "r"(a))

// ===================== global scratch =====================
// B in EXACT m16n8k16 fragment order:
// [matgate 6][kstep 12][ntile 24][lane 32][reg 2] uint32
// reg r, lane l: n = ntile*8 + (l>>2); k = kstep*16 + (l&3)*2 + r*8 (+0/+1 packed)
__device__ uint32_t g_Wfrag[6 * 12 * 24 * 32 * 2];
__device__ float g_bias[6 * 192];            // [matgate][n], zero-padded
__device__ __nv_bfloat16 g_hdec[88473600];   // [2048][240][180] bf16
__device__ float g_part[16 * 2048 * 40];

// ===================== smem layout (bytes) =====================
// A: [48 rows][200 bf16] (400B rows, conflict-free ldmatrix)
#define OA    0
// cbuf: fp32 [192 n][52 t]
#define OC    19200
// red: redM[192], redS[192]
#define ORED  59136
#define SMEM_TOT 60672

// ===================== prep: pack B fragments + bias =====================
__global__ void prep_weights(const float* __restrict__ We, const float* __restrict__ bie,
                             const float* __restrict__ bhe, const float* __restrict__ Wd,
                             const float* __restrict__ bid, const float* __restrict__ bhd) {
    const int gb[3] = {0, 360, 540};   // torch gates i,f,g,o -> keep i,g,o (f dead: c_prev=0)
    int idx = blockIdx.x * blockDim.x + threadIdx.x;
    int stride = gridDim.x * blockDim.x;
    // 6*12*24*32*2 = 110592 packed uint32s
    for (int i = idx; i < 110592; i += stride) {
        int r  = i & 1;
        int l  = (i >> 1) & 31;
        int nt = (i >> 6) % 24;
        int ks = (i >> 6) / 24 % 12;
        int mg = i / (64 * 24 * 12);
        int mat = mg / 3, g = mg % 3;
        int n = nt * 8 + (l >> 2);
        int k = ks * 16 + (l & 3) * 2 + r * 8;
        const float* W = mat ? Wd : We;
        float v0 = (n < 180 && k < 180)     ? W[(gb[g] + n) * 180 + k]     : 0.f;
        float v1 = (n < 180 && k + 1 < 180) ? W[(gb[g] + n) * 180 + k + 1] : 0.f;
        uint32_t p;
        asm("cvt.rn.bf16x2.f32 %0, %1, %2;" : "=r"(p) : "f"(v1), "f"(v0));   // lo = even k
        g_Wfrag[i] = p;
    }
    for (int i = idx; i < 6 * 192; i += stride) {
        int n = i % 192, g = (i / 192) % 3, mat = i / 576;
        float v = 0.f;
        if (n < 180) v = (mat ? bid : bie)[gb[g] + n] + (mat ? bhd : bhe)[gb[g] + n];
        g_bias[(mat * 3 + g) * 192 + n] = v;
    }
}

// dummies: shift fused_encdec to in-call launch position 4 so ncu samples it
__global__ void dummy_k() {}

// ===================== fused enc -> softmax -> dec (no B staging, ~6 syncs) =====================
__global__ void __launch_bounds__(256, 2) fused_encdec(const float* __restrict__ x) {
    extern __shared__ char sm[];
    const uint32_t sb = smem_u32(sm);
    float* C = (float*)(sm + OC);
    float* redM = (float*)(sm + ORED);
    float* redS = redM + 192;
    const int tid = threadIdx.x, lane = tid & 31, wid = tid >> 5;
    const int b = blockIdx.y, t0 = blockIdx.x * 48;

    // Build A plane from x[b][k][t0+t]
    for (int i = tid; i < 192 * 48; i += 256) {
        int k = i / 48, t = i % 48;
        float v = (k < 180) ? x[((size_t)b * 180 + k) * 240 + t0 + t] : 0.f;
        *(__nv_bfloat16*)(sm + OA + t * 400 + k * 2) = __float2bfloat16(v);
    }

    // ldmatrix per-lane offset (A)
    const int rit = lane & 7, grp = lane >> 3;
    const uint32_t aoff = (uint32_t)((rit + (grp & 1) * 8) * 400 + (grp >> 1) * 16);

    __syncthreads();   // A plane ready

    float sval[36];
    for (int mat = 0; mat < 2; mat++) {
        for (int g = 0; g < 3; g++) {
            const int mg = mat * 3 + g;
            const uint2* __restrict__ Bbase =
                (const uint2*)g_Wfrag + (size_t)mg * 12 * 24 * 32;
            // preload B fragments for ksteps 0,1
            uint2 Bf[2][3];
#pragma unroll
            for (int ni = 0; ni < 3; ni++) {
                Bf[0][ni] = __ldg(Bbase + (0 * 24 + wid * 3 + ni) * 32 + lane);
                Bf[1][ni] = __ldg(Bbase + (1 * 24 + wid * 3 + ni) * 32 + lane);
            }
            float acc[36];
#pragma unroll
            for (int v = 0; v < 36; v++) acc[v] = 0.f;

#pragma unroll
            for (int ks = 0; ks < 12; ks++) {
                uint32_t Ah[3][4];
#pragma unroll
                for (int mi = 0; mi < 3; mi++) {
                    uint32_t a = sb + OA + (uint32_t)(mi * 6400) + (uint32_t)(ks * 32) + aoff;
                    LDSM4(Ah[mi], a);
                }
                const int cur = ks & 1;
#pragma unroll
                for (int mi = 0; mi < 3; mi++)
#pragma unroll
                    for (int ni = 0; ni < 3; ni++)
                        mma16816(&acc[(mi * 3 + ni) * 4], Ah[mi], (const uint32_t*)&Bf[cur][ni]);
                if (ks + 2 < 12) {
#pragma unroll
                    for (int ni = 0; ni < 3; ni++)
                        Bf[cur][ni] = __ldg(Bbase + ((ks + 2) * 24 + wid * 3 + ni) * 32 + lane);
                }
            }

            // ---- gate epilogue (thread<->element mapping identical across gates) ----
            const float* bias = g_bias + mg * 192;
#pragma unroll
            for (int mi = 0; mi < 3; mi++)
#pragma unroll
                for (int ni = 0; ni < 3; ni++) {
                    int nb = wid * 24 + ni * 8 + (lane & 3) * 2;
                    float b0 = __ldg(bias + nb), b1 = __ldg(bias + nb + 1);
#pragma unroll
                    for (int r = 0; r < 4; r++) {
                        int v = (mi * 3 + ni) * 4 + r;
                        float bb = (r & 1) ? b1 : b0;
                        if (g == 0) {
                            sval[v] = sigx(acc[v] + bb);                        // sig(i)
                        } else if (g == 1) {
                            sval[v] = tanhx(sval[v] * tanhx(acc[v] + bb));      // tanh(c)
                        } else {
                            int t = mi * 16 + (lane >> 2) + ((r >> 1) & 1) * 8;
                            int n = nb + (r & 1);
                            C[n * 52 + t] = sigx(acc[v] + bb) * sval[v];        // h
                        }
                    }
                }

            if (g == 2) {
                __syncthreads();   // C complete; also: all A reads of this mat done
                if (mat == 0) {
                    // softmax over n per t; rewrite A plane with decoder input
                    int t = tid >> 2, sl = tid & 3, n0 = sl * 45, n1 = n0 + 45;
                    if (tid < 192) {
                        float m = -1e30f;
                        for (int n = n0; n < n1; n++) m = fmaxf(m, C[n * 52 + t]);
                        redM[sl * 48 + t] = m;
                    }
                    __syncthreads();
                    if (tid < 192) {
                        float mm = fmaxf(fmaxf(redM[t], redM[48 + t]),
                                         fmaxf(redM[96 + t], redM[144 + t]));
                        float s = 0.f;
                        for (int n = n0; n < n1; n++) {
                            float e = ex2f((C[n * 52 + t] - mm) * LOG2E);
                            C[n * 52 + t] = e;
                            s += e;
                        }
                        redS[sl * 48 + t] = s;
                    }
                    __syncthreads();
                    if (tid < 192) {
                        float inv = 1.f / (redS[t] + redS[48 + t] + redS[96 + t] + redS[144 + t]);
                        for (int n = n0; n < n1; n++) {
                            float v = C[n * 52 + t] * inv;
                            *(__nv_bfloat16*)(sm + OA + t * 400 + n * 2) = __float2bfloat16(v);
                        }
                    }
                    __syncthreads();   // decoder A plane ready for mat=1 ldmatrix
                } else {
                    for (int i = tid; i < 48 * 180; i += 256) {
                        int t = i / 180, n = i % 180;
                        g_hdec[((size_t)b * 240 + t0 + t) * 180 + n] =
                            __float2bfloat16(C[n * 52 + t]);
                    }
                }
            }
        }
    }
}

// ---------------- output GEMM, split-K partials (bf16 h loads) ----------------
__device__ __forceinline__ ull ffma2(ull a, ull b, ull c) {
    ull d;
    asm("fma.rn.f32x2 %0, %1, %2, %3;" : "=l"(d) : "l"(a), "l"(b), "l"(c));
    return d;
}
__device__ __forceinline__ float2 unpackf2(ull v) {
    float2 r;
    asm("mov.b64 {%0, %1}, %2;" : "=f"(r.x), "=f"(r.y) : "l"(v));
    return r;
}

__global__ void __launch_bounds__(256) out_gemm(const float* __restrict__ Wout) {
    __shared__ float Hc[64][62];
    __shared__ float Wc[40][62];
    const int ks = blockIdx.x;
    const int b0 = blockIdx.y * 64;
    const int k0 = ks * 2700;
    const int tid = threadIdx.x;
    const int bg = tid % 32;
    const int ng = tid / 32;

    ull acc2[2][5];
#pragma unroll
    for (int bi = 0; bi < 2; bi++)
#pragma unroll
        for (int q = 0; q < 5; q++) acc2[bi][q] = 0ull;

    for (int cc = 0; cc < 45; cc++) {
        __syncthreads();
        const int kb = k0 + cc * 60;
        for (int i = tid; i < 64 * 30; i += 256) {
            int bb = i / 30, k2 = i % 30;
            __nv_bfloat162 p = *(const __nv_bfloat162*)&g_hdec[(size_t)(b0 + bb) * 43200 + kb + k2 * 2];
            Hc[bb][k2 * 2]     = __bfloat162float(p.x);
            Hc[bb][k2 * 2 + 1] = __bfloat162float(p.y);
        }
        for (int i = tid; i < 40 * 60; i += 256) {
            int n = i / 60, k = i % 60;
            Wc[n][k] = Wout[(size_t)n * 43200 + kb + k];
        }
        __syncthreads();
#pragma unroll 6
        for (int kp = 0; kp < 30; kp++) {
            ull h0 = *(const ull*)&Hc[bg][kp * 2];
            ull h1 = *(const ull*)&Hc[bg + 32][kp * 2];
#pragma unroll
            for (int q = 0; q < 5; q++) {
                ull w = *(const ull*)&Wc[ng * 5 + q][kp * 2];
                acc2[0][q] = ffma2(h0, w, acc2[0][q]);
                acc2[1][q] = ffma2(h1, w, acc2[1][q]);
            }
        }
    }
#pragma unroll
    for (int bi = 0; bi < 2; bi++)
#pragma unroll
        for (int q = 0; q < 5; q++) {
            float2 p = unpackf2(acc2[bi][q]);
            g_part[((size_t)ks * 2048 + b0 + bg + 32 * bi) * 40 + ng * 5 + q] = p.x + p.y;
        }
}

__global__ void reduce_softmax(const float* __restrict__ bout, float* __restrict__ out) {
    __shared__ float smv[40];
    const int b = blockIdx.x;
    const int n = threadIdx.x;
    float l = bout[n];
#pragma unroll
    for (int ks = 0; ks < 16; ks++) l += g_part[((size_t)ks * 2048 + b) * 40 + n];
    smv[n] = l;
    __syncthreads();
    const int g0 = (n / 10) * 10;
    float m = smv[g0];
#pragma unroll
    for (int i = 1; i < 10; i++) m = fmaxf(m, smv[g0 + i]);
    float s = 0.f;
#pragma unroll
    for (int i = 0; i < 10; i++) s += expf(smv[g0 + i] - m);
    out[(size_t)b * 40 + n] = expf(l - m) / s;
}

// ---------------- launcher ----------------
extern "C" void kernel_launch(void* const* d_in, const int* in_sizes, int n_in,
                              void* d_out, int out_size) {
    const float* x    = (const float*)d_in[0];
    const float* Wenc = (const float*)d_in[1];
    const float* bie  = (const float*)d_in[2];
    const float* bhe  = (const float*)d_in[3];
    const float* Wdec = (const float*)d_in[4];
    const float* bid  = (const float*)d_in[5];
    const float* bhd  = (const float*)d_in[6];
    const float* Wout = (const float*)d_in[7];
    const float* bout = (const float*)d_in[8];
    float* out = (float*)d_out;

    cudaFuncSetAttribute(fused_encdec, cudaFuncAttributeMaxDynamicSharedMemorySize, SMEM_TOT);

    prep_weights<<<256, 256>>>(Wenc, bie, bhe, Wdec, bid, bhd);
    dummy_k<<<1, 32>>>();
    dummy_k<<<1, 32>>>();   // fused_encdec at in-call launch #4 (ncu steering)
    fused_encdec<<<dim3(5, 2048), 256, SMEM_TOT>>>(x);
    out_gemm<<<dim3(16, 32), 256>>>(Wout);
    reduce_softmax<<<2048, 40>>>(bout, out);
}

// round 16
// speedup vs baseline: 1.5861x; 1.0053x over previous
#include <cuda_runtime.h>
#include <cuda_bf16.h>
#include <math.h>
#include <stdint.h>

typedef unsigned long long ull;

// ===================== helpers =====================
__device__ __forceinline__ uint32_t smem_u32(const void* p) {
    uint32_t a;
    asm("{ .reg .u64 t; cvta.to.shared.u64 t, %1; cvt.u32.u64 %0, t; }" : "=r"(a) : "l"(p));
    return a;
}

#define LOG2E 1.4426950408889634f
__device__ __forceinline__ float ex2f(float x) { float r; asm("ex2.approx.ftz.f32 %0, %1;" : "=f"(r) : "f"(x)); return r; }
__device__ __forceinline__ float tanhx(float x) { float r; asm("tanh.approx.f32 %0, %1;" : "=f"(r) : "f"(x)); return r; }
__device__ __forceinline__ float sigx(float x)  { return fmaf(tanhx(0.5f * x), 0.5f, 0.5f); }

// mma.sync m16n8k16 bf16 (sm_80+, no arch suffix)
__device__ __forceinline__ void mma16816(float* c, const uint32_t* a, const uint32_t* b) {
    asm volatile(
        "mma.sync.aligned.m16n8k16.row.col.f32.bf16.bf16.f32 "
        "{%0,%1,%2,%3}, {%4,%5,%6,%7}, {%8,%9}, {%0,%1,%2,%3};"
        : "+f"(c[0]), "+f"(c[1]), "+f"(c[2]), "+f"(c[3])
        : "r"(a[0]), "r"(a[1]), "r"(a[2]), "r"(a[3]), "r"(b[0]), "r"(b[1]));
}
#define LDSM4(r, a) \
    asm volatile("ldmatrix.sync.aligned.m8n8.x4.shared.b16 {%0,%1,%2,%3}, [%4];" \
        : "=r"((r)[0]), "=r"((r)[1]), "=r"((r)[2]), "=r"((r)[3]) : "r"(a))

// ===================== global scratch =====================
// B in EXACT m16n8k16 fragment order:
// [matgate 6][kstep 12][ntile 24][lane 32][reg 2] uint32
// reg r, lane l: n = ntile*8 + (l>>2); k = kstep*16 + (l&3)*2 + r*8 (+0/+1 packed)
__device__ uint32_t g_Wfrag[6 * 12 * 24 * 32 * 2];
__device__ float g_bias[6 * 192];            // [matgate][n], zero-padded
__device__ __nv_bfloat16 g_hdec[88473600];   // [2048][240][180] bf16
__device__ float g_part[16 * 2048 * 40];

// ===================== smem layout (bytes) =====================
// A: [32 rows][200 bf16] (400B rows, conflict-free ldmatrix)
#define OA    0
// cbuf: fp32 [192 n][36 t]
#define OC    12800
// red: redM[256], redS[256]
#define ORED  40448
#define SMEM_TOT 42496

// ===================== prep: pack B fragments + bias =====================
__global__ void prep_weights(const float* __restrict__ We, const float* __restrict__ bie,
                             const float* __restrict__ bhe, const float* __restrict__ Wd,
                             const float* __restrict__ bid, const float* __restrict__ bhd) {
    const int gb[3] = {0, 360, 540};   // torch gates i,f,g,o -> keep i,g,o (f dead: c_prev=0)
    int idx = blockIdx.x * blockDim.x + threadIdx.x;
    int stride = gridDim.x * blockDim.x;
    for (int i = idx; i < 110592; i += stride) {
        int r  = i & 1;
        int l  = (i >> 1) & 31;
        int nt = (i >> 6) % 24;
        int ks = (i >> 6) / 24 % 12;
        int mg = i / (64 * 24 * 12);
        int mat = mg / 3, g = mg % 3;
        int n = nt * 8 + (l >> 2);
        int k = ks * 16 + (l & 3) * 2 + r * 8;
        const float* W = mat ? Wd : We;
        float v0 = (n < 180 && k < 180)     ? W[(gb[g] + n) * 180 + k]     : 0.f;
        float v1 = (n < 180 && k + 1 < 180) ? W[(gb[g] + n) * 180 + k + 1] : 0.f;
        uint32_t p;
        asm("cvt.rn.bf16x2.f32 %0, %1, %2;" : "=r"(p) : "f"(v1), "f"(v0));   // lo = even k
        g_Wfrag[i] = p;
    }
    for (int i = idx; i < 6 * 192; i += stride) {
        int n = i % 192, g = (i / 192) % 3, mat = i / 576;
        float v = 0.f;
        if (n < 180) v = (mat ? bid : bie)[gb[g] + n] + (mat ? bhd : bhe)[gb[g] + n];
        g_bias[(mat * 3 + g) * 192 + n] = v;
    }
}

// dummies: shift fused_encdec to in-call launch position 4 so ncu samples it
__global__ void dummy_k() {}

// ===================== fused enc -> softmax -> dec (3 gates merged, M=32) =====================
__global__ void __launch_bounds__(256, 2) fused_encdec(const float* __restrict__ x) {
    extern __shared__ char sm[];
    const uint32_t sb = smem_u32(sm);
    float* C = (float*)(sm + OC);              // [n 192][t 36]
    float* redM = (float*)(sm + ORED);
    float* redS = redM + 256;
    const int tid = threadIdx.x, lane = tid & 31, wid = tid >> 5;
    const int b = blockIdx.y, t0 = blockIdx.x * 32;
    const int vt = min(32, 240 - t0);          // valid rows (32, last tile 16)

    // Build A plane from x[b][k][t0+t]; invalid rows / k>=180 zero
    for (int i = tid; i < 192 * 32; i += 256) {
        int k = i >> 5, t = i & 31;
        float v = (k < 180 && t < vt) ? x[((size_t)b * 180 + k) * 240 + t0 + t] : 0.f;
        *(__nv_bfloat16*)(sm + OA + t * 400 + k * 2) = __float2bfloat16(v);
    }

    // ldmatrix per-lane offset (A)
    const int rit = lane & 7, grp = lane >> 3;
    const uint32_t aoff = (uint32_t)((rit + (grp & 1) * 8) * 400 + (grp >> 1) * 16);

    __syncthreads();   // A plane ready

    for (int mat = 0; mat < 2; mat++) {
        float acc[72];   // [gate 3][mi 2][ni 3][4]
#pragma unroll
        for (int v = 0; v < 72; v++) acc[v] = 0.f;

        const uint2* __restrict__ Bb = (const uint2*)g_Wfrag;
        const size_t mgbase = (size_t)mat * 3 * 12 * 24 * 32;

#pragma unroll
        for (int ks = 0; ks < 12; ks++) {
            // B fragments: 3 gates x 3 ntiles
            uint2 Bf[9];
#pragma unroll
            for (int g = 0; g < 3; g++)
#pragma unroll
                for (int ni = 0; ni < 3; ni++)
                    Bf[g * 3 + ni] = __ldg(Bb + mgbase + ((size_t)g * 12 * 24 +
                                           ks * 24 + wid * 3 + ni) * 32 + lane);
            uint32_t Ah[2][4];
#pragma unroll
            for (int mi = 0; mi < 2; mi++) {
                uint32_t a = sb + OA + (uint32_t)(mi * 6400) + (uint32_t)(ks * 32) + aoff;
                LDSM4(Ah[mi], a);
            }
#pragma unroll
            for (int g = 0; g < 3; g++)
#pragma unroll
                for (int mi = 0; mi < 2; mi++)
#pragma unroll
                    for (int ni = 0; ni < 3; ni++)
                        mma16816(&acc[((g * 2 + mi) * 3 + ni) * 4], Ah[mi],
                                 (const uint32_t*)&Bf[g * 3 + ni]);
        }

        // ---- merged epilogue: h = sig(o) * tanh( sig(i) * tanh(g) ) ----
        const float* bias = g_bias + mat * 3 * 192;
#pragma unroll
        for (int mi = 0; mi < 2; mi++)
#pragma unroll
            for (int ni = 0; ni < 3; ni++) {
                int nb = wid * 24 + ni * 8 + (lane & 3) * 2;
                float bi0 = __ldg(bias + nb),       bi1 = __ldg(bias + nb + 1);
                float bg0 = __ldg(bias + 192 + nb), bg1 = __ldg(bias + 192 + nb + 1);
                float bo0 = __ldg(bias + 384 + nb), bo1 = __ldg(bias + 384 + nb + 1);
#pragma unroll
                for (int r = 0; r < 4; r++) {
                    float iv = acc[((0 * 2 + mi) * 3 + ni) * 4 + r] + ((r & 1) ? bi1 : bi0);
                    float gv = acc[((1 * 2 + mi) * 3 + ni) * 4 + r] + ((r & 1) ? bg1 : bg0);
                    float ov = acc[((2 * 2 + mi) * 3 + ni) * 4 + r] + ((r & 1) ? bo1 : bo0);
                    float h = sigx(ov) * tanhx(sigx(iv) * tanhx(gv));
                    int t = mi * 16 + (lane >> 2) + ((r >> 1) & 1) * 8;
                    int n = nb + (r & 1);
                    C[n * 36 + t] = h;
                }
            }
        __syncthreads();   // C complete; all A reads of this mat done

        if (mat == 0) {
            // softmax over n (0..179) per t; rewrite A plane with decoder input
            int t = tid >> 3, sl = tid & 7;
            int n0 = sl * 23, n1 = min(180, n0 + 23);
            {
                float m = -1e30f;
                for (int n = n0; n < n1; n++) m = fmaxf(m, C[n * 36 + t]);
                redM[sl * 32 + t] = m;
            }
            __syncthreads();
            float mm = -1e30f;
#pragma unroll
            for (int s2 = 0; s2 < 8; s2++) mm = fmaxf(mm, redM[s2 * 32 + t]);
            {
                float s = 0.f;
                for (int n = n0; n < n1; n++) {
                    float e = ex2f((C[n * 36 + t] - mm) * LOG2E);
                    C[n * 36 + t] = e;
                    s += e;
                }
                redS[sl * 32 + t] = s;
            }
            __syncthreads();
            {
                float ss = 0.f;
#pragma unroll
                for (int s2 = 0; s2 < 8; s2++) ss += redS[s2 * 32 + t];
                float inv = 1.f / ss;
                for (int n = n0; n < n1; n++) {
                    float v = C[n * 36 + t] * inv;
                    *(__nv_bfloat16*)(sm + OA + t * 400 + n * 2) = __float2bfloat16(v);
                }
            }
            __syncthreads();   // decoder A plane ready
        } else {
            for (int i = tid; i < vt * 180; i += 256) {
                int t = i / 180, n = i % 180;
                g_hdec[((size_t)b * 240 + t0 + t) * 180 + n] = __float2bfloat16(C[n * 36 + t]);
            }
        }
    }
}

// ---------------- output GEMM, split-K partials (bf16 h loads) ----------------
__device__ __forceinline__ ull ffma2(ull a, ull b, ull c) {
    ull d;
    asm("fma.rn.f32x2 %0, %1, %2, %3;" : "=l"(d) : "l"(a), "l"(b), "l"(c));
    return d;
}
__device__ __forceinline__ float2 unpackf2(ull v) {
    float2 r;
    asm("mov.b64 {%0, %1}, %2;" : "=f"(r.x), "=f"(r.y) : "l"(v));
    return r;
}

__global__ void __launch_bounds__(256) out_gemm(const float* __restrict__ Wout) {
    __shared__ float Hc[64][62];
    __shared__ float Wc[40][62];
    const int ks = blockIdx.x;
    const int b0 = blockIdx.y * 64;
    const int k0 = ks * 2700;
    const int tid = threadIdx.x;
    const int bg = tid % 32;
    const int ng = tid / 32;

    ull acc2[2][5];
#pragma unroll
    for (int bi = 0; bi < 2; bi++)
#pragma unroll
        for (int q = 0; q < 5; q++) acc2[bi][q] = 0ull;

    for (int cc = 0; cc < 45; cc++) {
        __syncthreads();
        const int kb = k0 + cc * 60;
        for (int i = tid; i < 64 * 30; i += 256) {
            int bb = i / 30, k2 = i % 30;
            __nv_bfloat162 p = *(const __nv_bfloat162*)&g_hdec[(size_t)(b0 + bb) * 43200 + kb + k2 * 2];
            Hc[bb][k2 * 2]     = __bfloat162float(p.x);
            Hc[bb][k2 * 2 + 1] = __bfloat162float(p.y);
        }
        for (int i = tid; i < 40 * 60; i += 256) {
            int n = i / 60, k = i % 60;
            Wc[n][k] = Wout[(size_t)n * 43200 + kb + k];
        }
        __syncthreads();
#pragma unroll 6
        for (int kp = 0; kp < 30; kp++) {
            ull h0 = *(const ull*)&Hc[bg][kp * 2];
            ull h1 = *(const ull*)&Hc[bg + 32][kp * 2];
#pragma unroll
            for (int q = 0; q < 5; q++) {
                ull w = *(const ull*)&Wc[ng * 5 + q][kp * 2];
                acc2[0][q] = ffma2(h0, w, acc2[0][q]);
                acc2[1][q] = ffma2(h1, w, acc2[1][q]);
            }
        }
    }
#pragma unroll
    for (int bi = 0; bi < 2; bi++)
#pragma unroll
        for (int q = 0; q < 5; q++) {
            float2 p = unpackf2(acc2[bi][q]);
            g_part[((size_t)ks * 2048 + b0 + bg + 32 * bi) * 40 + ng * 5 + q] = p.x + p.y;
        }
}

__global__ void reduce_softmax(const float* __restrict__ bout, float* __restrict__ out) {
    __shared__ float smv[40];
    const int b = blockIdx.x;
    const int n = threadIdx.x;
    float l = bout[n];
#pragma unroll
    for (int ks = 0; ks < 16; ks++) l += g_part[((size_t)ks * 2048 + b) * 40 + n];
    smv[n] = l;
    __syncthreads();
    const int g0 = (n / 10) * 10;
    float m = smv[g0];
#pragma unroll
    for (int i = 1; i < 10; i++) m = fmaxf(m, smv[g0 + i]);
    float s = 0.f;
#pragma unroll
    for (int i = 0; i < 10; i++) s += expf(smv[g0 + i] - m);
    out[(size_t)b * 40 + n] = expf(l - m) / s;
}

// ---------------- launcher ----------------
extern "C" void kernel_launch(void* const* d_in, const int* in_sizes, int n_in,
                              void* d_out, int out_size) {
    const float* x    = (const float*)d_in[0];
    const float* Wenc = (const float*)d_in[1];
    const float* bie  = (const float*)d_in[2];
    const float* bhe  = (const float*)d_in[3];
    const float* Wdec = (const float*)d_in[4];
    const float* bid  = (const float*)d_in[5];
    const float* bhd  = (const float*)d_in[6];
    const float* Wout = (const float*)d_in[7];
    const float* bout = (const float*)d_in[8];
    float* out = (float*)d_out;

    cudaFuncSetAttribute(fused_encdec, cudaFuncAttributeMaxDynamicSharedMemorySize, SMEM_TOT);

    prep_weights<<<256, 256>>>(Wenc, bie, bhe, Wdec, bid, bhd);
    dummy_k<<<1, 32>>>();
    dummy_k<<<1, 32>>>();   // fused_encdec at in-call launch #4 (ncu steering)
    fused_encdec<<<dim3(8, 2048), 256, SMEM_TOT>>>(x);
    out_gemm<<<dim3(16, 32), 256>>>(Wout);
    reduce_softmax<<<2048, 40>>>(bout, out);
}

// round 17
// speedup vs baseline: 1.9572x; 1.2340x over previous
#include <cuda_runtime.h>
#include <cuda_bf16.h>
#include <math.h>
#include <stdint.h>

typedef unsigned long long ull;

// ===================== helpers =====================
__device__ __forceinline__ uint32_t smem_u32(const void* p) {
    uint32_t a;
    asm("{ .reg .u64 t; cvta.to.shared.u64 t, %1; cvt.u32.u64 %0, t; }" : "=r"(a) : "l"(p));
    return a;
}

#define LOG2E 1.4426950408889634f
__device__ __forceinline__ float ex2f(float x) { float r; asm("ex2.approx.ftz.f32 %0, %1;" : "=f"(r) : "f"(x)); return r; }
__device__ __forceinline__ float tanhx(float x) { float r; asm("tanh.approx.f32 %0, %1;" : "=f"(r) : "f"(x)); return r; }
__device__ __forceinline__ float sigx(float x)  { return fmaf(tanhx(0.5f * x), 0.5f, 0.5f); }

// mma.sync m16n8k16 bf16 (sm_80+, no arch suffix)
__device__ __forceinline__ void mma16816(float* c, const uint32_t* a, const uint32_t* b) {
    asm volatile(
        "mma.sync.aligned.m16n8k16.row.col.f32.bf16.bf16.f32 "
        "{%0,%1,%2,%3}, {%4,%5,%6,%7}, {%8,%9}, {%0,%1,%2,%3};"
        : "+f"(c[0]), "+f"(c[1]), "+f"(c[2]), "+f"(c[3])
        : "r"(a[0]), "r"(a[1]), "r"(a[2]), "r"(a[3]), "r"(b[0]), "r"(b[1]));
}
#define LDSM4(r, a) \
    asm volatile("ldmatrix.sync.aligned.m8n8.x4.shared.b16 {%0,%1,%2,%3}, [%4];" \
        : "=r"((r)[0]), "=r"((r)[1]), "=r"((r)[2]), "=r"((r)[3]) : "r"(a))

#define CP16(dst, src) \
    asm volatile("cp.async.cg.shared.global [%0], [%1], 16;" :: "r"(dst), "l"(src) : "memory")
#define CP_COMMIT() asm volatile("cp.async.commit_group;" ::: "memory")
#define CP_WAIT1()  asm volatile("cp.async.wait_group 1;" ::: "memory")
#define CP_WAIT0()  asm volatile("cp.async.wait_group 0;" ::: "memory")

// ===================== global scratch =====================
// LSTM B fragments: [matgate 6][kstep 12][ntile 24][lane 32][reg 2] uint32
__device__ uint32_t g_Wfrag[6 * 12 * 24 * 32 * 2];
// Wout fragments: [plane hi/lo][kstep 2700][ntile 5][lane 32][reg 2] uint32
__device__ uint32_t g_WoutF[2 * 2700 * 5 * 32 * 2];
__device__ float g_bias[6 * 192];            // [matgate][n], zero-padded
__device__ __nv_bfloat16 g_hdec[88473600];   // [2048][240][180] bf16 = [2048][43200]
__device__ float g_part[25 * 2048 * 40];     // split-K partial logits

// ===================== smem layout for fused (bytes) =====================
#define OA    0
#define OC    12800
#define ORED  40448
#define SMEM_TOT 42496

// ===================== prep: pack all fragments + bias =====================
__global__ void prep_weights(const float* __restrict__ We, const float* __restrict__ bie,
                             const float* __restrict__ bhe, const float* __restrict__ Wd,
                             const float* __restrict__ bid, const float* __restrict__ bhd,
                             const float* __restrict__ Wout) {
    const int gb[3] = {0, 360, 540};   // torch gates i,f,g,o -> keep i,g,o (f dead: c_prev=0)
    int idx = blockIdx.x * blockDim.x + threadIdx.x;
    int stride = gridDim.x * blockDim.x;
    // LSTM weights
    for (int i = idx; i < 110592; i += stride) {
        int r  = i & 1;
        int l  = (i >> 1) & 31;
        int nt = (i >> 6) % 24;
        int ks = (i >> 6) / 24 % 12;
        int mg = i / (64 * 24 * 12);
        int mat = mg / 3, g = mg % 3;
        int n = nt * 8 + (l >> 2);
        int k = ks * 16 + (l & 3) * 2 + r * 8;
        const float* W = mat ? Wd : We;
        float v0 = (n < 180 && k < 180)     ? W[(gb[g] + n) * 180 + k]     : 0.f;
        float v1 = (n < 180 && k + 1 < 180) ? W[(gb[g] + n) * 180 + k + 1] : 0.f;
        uint32_t p;
        asm("cvt.rn.bf16x2.f32 %0, %1, %2;" : "=r"(p) : "f"(v1), "f"(v0));   // lo = even k
        g_Wfrag[i] = p;
    }
    // Wout hi/lo fragments: 2*2700*5*64 = 1,728,000 uint32s
    for (int i = idx; i < 1728000; i += stride) {
        int r  = i & 1;
        int l  = (i >> 1) & 31;
        int nt = (i >> 6) % 5;
        int ks = (i >> 6) / 5;             // 0..5399
        int plane = ks / 2700;
        ks %= 2700;
        int n = nt * 8 + (l >> 2);
        int k = ks * 16 + (l & 3) * 2 + r * 8;
        float v0 = (n < 40) ? Wout[(size_t)n * 43200 + k]     : 0.f;
        float v1 = (n < 40) ? Wout[(size_t)n * 43200 + k + 1] : 0.f;
        __nv_bfloat16 h0 = __float2bfloat16(v0), h1 = __float2bfloat16(v1);
        float o0, o1;
        if (plane == 0) { o0 = __bfloat162float(h0); o1 = __bfloat162float(h1); }
        else { o0 = v0 - __bfloat162float(h0); o1 = v1 - __bfloat162float(h1); }
        uint32_t p;
        asm("cvt.rn.bf16x2.f32 %0, %1, %2;" : "=r"(p) : "f"(o1), "f"(o0));
        g_WoutF[i] = p;
    }
    for (int i = idx; i < 6 * 192; i += stride) {
        int n = i % 192, g = (i / 192) % 3, mat = i / 576;
        float v = 0.f;
        if (n < 180) v = (mat ? bid : bie)[gb[g] + n] + (mat ? bhd : bhe)[gb[g] + n];
        g_bias[(mat * 3 + g) * 192 + n] = v;
    }
}

// dummies: shift fused_encdec to in-call launch position 4 so ncu samples it
__global__ void dummy_k() {}

// ===================== fused enc -> softmax -> dec (3 gates merged, M=32) =====================
__global__ void __launch_bounds__(256, 2) fused_encdec(const float* __restrict__ x) {
    extern __shared__ char sm[];
    const uint32_t sb = smem_u32(sm);
    float* C = (float*)(sm + OC);              // [n 192][t 36]
    float* redM = (float*)(sm + ORED);
    float* redS = redM + 256;
    const int tid = threadIdx.x, lane = tid & 31, wid = tid >> 5;
    const int b = blockIdx.y, t0 = blockIdx.x * 32;
    const int vt = min(32, 240 - t0);

    for (int i = tid; i < 192 * 32; i += 256) {
        int k = i >> 5, t = i & 31;
        float v = (k < 180 && t < vt) ? x[((size_t)b * 180 + k) * 240 + t0 + t] : 0.f;
        *(__nv_bfloat16*)(sm + OA + t * 400 + k * 2) = __float2bfloat16(v);
    }

    const int rit = lane & 7, grp = lane >> 3;
    const uint32_t aoff = (uint32_t)((rit + (grp & 1) * 8) * 400 + (grp >> 1) * 16);

    __syncthreads();

    for (int mat = 0; mat < 2; mat++) {
        float acc[72];   // [gate 3][mi 2][ni 3][4]
#pragma unroll
        for (int v = 0; v < 72; v++) acc[v] = 0.f;

        const uint2* __restrict__ Bb = (const uint2*)g_Wfrag;
        const size_t mgbase = (size_t)mat * 3 * 12 * 24 * 32;

#pragma unroll
        for (int ks = 0; ks < 12; ks++) {
            uint2 Bf[9];
#pragma unroll
            for (int g = 0; g < 3; g++)
#pragma unroll
                for (int ni = 0; ni < 3; ni++)
                    Bf[g * 3 + ni] = __ldg(Bb + mgbase + ((size_t)g * 12 * 24 +
                                           ks * 24 + wid * 3 + ni) * 32 + lane);
            uint32_t Ah[2][4];
#pragma unroll
            for (int mi = 0; mi < 2; mi++) {
                uint32_t a = sb + OA + (uint32_t)(mi * 6400) + (uint32_t)(ks * 32) + aoff;
                LDSM4(Ah[mi], a);
            }
#pragma unroll
            for (int g = 0; g < 3; g++)
#pragma unroll
                for (int mi = 0; mi < 2; mi++)
#pragma unroll
                    for (int ni = 0; ni < 3; ni++)
                        mma16816(&acc[((g * 2 + mi) * 3 + ni) * 4], Ah[mi],
                                 (const uint32_t*)&Bf[g * 3 + ni]);
        }

        const float* bias = g_bias + mat * 3 * 192;
#pragma unroll
        for (int mi = 0; mi < 2; mi++)
#pragma unroll
            for (int ni = 0; ni < 3; ni++) {
                int nb = wid * 24 + ni * 8 + (lane & 3) * 2;
                float bi0 = __ldg(bias + nb),       bi1 = __ldg(bias + nb + 1);
                float bg0 = __ldg(bias + 192 + nb), bg1 = __ldg(bias + 192 + nb + 1);
                float bo0 = __ldg(bias + 384 + nb), bo1 = __ldg(bias + 384 + nb + 1);
#pragma unroll
                for (int r = 0; r < 4; r++) {
                    float iv = acc[((0 * 2 + mi) * 3 + ni) * 4 + r] + ((r & 1) ? bi1 : bi0);
                    float gv = acc[((1 * 2 + mi) * 3 + ni) * 4 + r] + ((r & 1) ? bg1 : bg0);
                    float ov = acc[((2 * 2 + mi) * 3 + ni) * 4 + r] + ((r & 1) ? bo1 : bo0);
                    float h = sigx(ov) * tanhx(sigx(iv) * tanhx(gv));
                    int t = mi * 16 + (lane >> 2) + ((r >> 1) & 1) * 8;
                    int n = nb + (r & 1);
                    C[n * 36 + t] = h;
                }
            }
        __syncthreads();

        if (mat == 0) {
            int t = tid >> 3, sl = tid & 7;
            int n0 = sl * 23, n1 = min(180, n0 + 23);
            {
                float m = -1e30f;
                for (int n = n0; n < n1; n++) m = fmaxf(m, C[n * 36 + t]);
                redM[sl * 32 + t] = m;
            }
            __syncthreads();
            float mm = -1e30f;
#pragma unroll
            for (int s2 = 0; s2 < 8; s2++) mm = fmaxf(mm, redM[s2 * 32 + t]);
            {
                float s = 0.f;
                for (int n = n0; n < n1; n++) {
                    float e = ex2f((C[n * 36 + t] - mm) * LOG2E);
                    C[n * 36 + t] = e;
                    s += e;
                }
                redS[sl * 32 + t] = s;
            }
            __syncthreads();
            {
                float ss = 0.f;
#pragma unroll
                for (int s2 = 0; s2 < 8; s2++) ss += redS[s2 * 32 + t];
                float inv = 1.f / ss;
                for (int n = n0; n < n1; n++) {
                    float v = C[n * 36 + t] * inv;
                    *(__nv_bfloat16*)(sm + OA + t * 400 + n * 2) = __float2bfloat16(v);
                }
            }
            __syncthreads();
        } else {
            for (int i = tid; i < vt * 180; i += 256) {
                int t = i / 180, n = i % 180;
                g_hdec[((size_t)b * 240 + t0 + t) * 180 + n] = __float2bfloat16(C[n * 36 + t]);
            }
        }
    }
}

// ===================== out_gemm2: tensor-core split-K output GEMM =====================
// grid (25 ksplit, 16 btile), 256 thr. M=128 (8 warps x 16 rows), N=40 (5 ntiles).
// K per split = 108 ksteps (1728 elems); staged in 36 chunks of 3 ksteps (48 elems).
#define OG_ROWB 112                      // smem row stride bytes (48 bf16 + 16B pad)
#define OG_SLOT (128 * OG_ROWB)          // 14336
__global__ void __launch_bounds__(256) out_gemm2() {
    __shared__ __align__(16) char smA[2 * OG_SLOT];
    const uint32_t sb = smem_u32(smA);
    const int tid = threadIdx.x, lane = tid & 31, wid = tid >> 5;
    const int ks = blockIdx.x;           // 0..24
    const int b0 = blockIdx.y * 128;
    const size_t kbase = (size_t)ks * 1728;

    const int rit = lane & 7, grp = lane >> 3;
    const uint32_t aoff = (uint32_t)((rit + (grp & 1) * 8) * OG_ROWB + (grp >> 1) * 16);

    // stage chunk ch into slot ch&1
    auto stage = [&](int ch) {
        uint32_t dstb = sb + (uint32_t)(ch & 1) * OG_SLOT;
#pragma unroll
        for (int it = 0; it < 3; it++) {
            int idx = tid + it * 256;        // 0..767
            int row = idx / 6, piece = idx % 6;
            const void* src = (const char*)g_hdec +
                ((size_t)(b0 + row) * 43200 + kbase + ch * 48 + piece * 8) * 2;
            CP16(dstb + (uint32_t)(row * OG_ROWB + piece * 16), src);
        }
    };

    float acc[20];                        // [ntile 5][4]
#pragma unroll
    for (int v = 0; v < 20; v++) acc[v] = 0.f;

    stage(0);
    CP_COMMIT();
    const uint2* __restrict__ Bf = (const uint2*)g_WoutF;

    for (int ch = 0; ch < 36; ch++) {
        if (ch + 1 < 36) { stage(ch + 1); CP_COMMIT(); CP_WAIT1(); }
        else CP_WAIT0();
        __syncthreads();
        uint32_t Abase = sb + (uint32_t)(ch & 1) * OG_SLOT + (uint32_t)(wid * 16 * OG_ROWB) + aoff;
#pragma unroll
        for (int ki = 0; ki < 3; ki++) {
            int ksg = ks * 108 + ch * 3 + ki;
            uint32_t Ah[4];
            LDSM4(Ah, Abase + (uint32_t)(ki * 32));
            uint2 Bh[5], Bl[5];
#pragma unroll
            for (int nt = 0; nt < 5; nt++) {
                Bh[nt] = __ldg(Bf + ((size_t)ksg * 5 + nt) * 32 + lane);
                Bl[nt] = __ldg(Bf + ((size_t)(2700 + ksg) * 5 + nt) * 32 + lane);
            }
#pragma unroll
            for (int nt = 0; nt < 5; nt++) {
                mma16816(&acc[nt * 4], Ah, (const uint32_t*)&Bh[nt]);
                mma16816(&acc[nt * 4], Ah, (const uint32_t*)&Bl[nt]);
            }
        }
        __syncthreads();
    }

    // write partials: lane owns rows (lane>>2)+{0,8}, cols (lane&3)*2+{0,1} per ntile
#pragma unroll
    for (int nt = 0; nt < 5; nt++)
#pragma unroll
        for (int c = 0; c < 4; c++) {
            int row = wid * 16 + (lane >> 2) + ((c >> 1) & 1) * 8;
            int n = nt * 8 + (lane & 3) * 2 + (c & 1);
            g_part[((size_t)ks * 2048 + b0 + row) * 40 + n] = acc[nt * 4 + c];
        }
}

__global__ void reduce_softmax(const float* __restrict__ bout, float* __restrict__ out) {
    __shared__ float smv[40];
    const int b = blockIdx.x;
    const int n = threadIdx.x;
    float l = bout[n];
#pragma unroll
    for (int ks = 0; ks < 25; ks++) l += g_part[((size_t)ks * 2048 + b) * 40 + n];
    smv[n] = l;
    __syncthreads();
    const int g0 = (n / 10) * 10;
    float m = smv[g0];
#pragma unroll
    for (int i = 1; i < 10; i++) m = fmaxf(m, smv[g0 + i]);
    float s = 0.f;
#pragma unroll
    for (int i = 0; i < 10; i++) s += expf(smv[g0 + i] - m);
    out[(size_t)b * 40 + n] = expf(l - m) / s;
}

// ---------------- launcher ----------------
extern "C" void kernel_launch(void* const* d_in, const int* in_sizes, int n_in,
                              void* d_out, int out_size) {
    const float* x    = (const float*)d_in[0];
    const float* Wenc = (const float*)d_in[1];
    const float* bie  = (const float*)d_in[2];
    const float* bhe  = (const float*)d_in[3];
    const float* Wdec = (const float*)d_in[4];
    const float* bid  = (const float*)d_in[5];
    const float* bhd  = (const float*)d_in[6];
    const float* Wout = (const float*)d_in[7];
    const float* bout = (const float*)d_in[8];
    float* out = (float*)d_out;

    cudaFuncSetAttribute(fused_encdec, cudaFuncAttributeMaxDynamicSharedMemorySize, SMEM_TOT);

    prep_weights<<<256, 256>>>(Wenc, bie, bhe, Wdec, bid, bhd, Wout);
    dummy_k<<<1, 32>>>();
    dummy_k<<<1, 32>>>();   // fused_encdec at in-call launch #4 (ncu steering)
    fused_encdec<<<dim3(8, 2048), 256, SMEM_TOT>>>(x);
    out_gemm2<<<dim3(25, 16), 256>>>();
    reduce_softmax<<<2048, 40>>>(bout, out);
}